// round 9
// baseline (speedup 1.0000x reference)
#include <cuda_runtime.h>
#include <cuda_bf16.h>
#include <cstdint>

// ---------------- problem constants ----------------
#define BATCH    4096
#define NDIMS    19
#define D        256
#define NROWS    8192
#define NBLK     64                    // 64 row-blocks of 128
#define NCTA     148
#define INV_T    14.285714285714286f
#define C2EXP    (14.285714285714286f * 1.4426950408889634f)   // INV_T * log2(e)
#define CAPR     32                    // positive slots per row
#define NTHREADS 512
#define TILEB    32768                 // 128 rows x 256 bytes (fp8)

// ---------------- device scratch ----------------
__device__ uint32_t g_Z8[NROWS * 64];         // normalized e4m3 rows (4 per u32)
__device__ int      g_pieces[NROWS];
__device__ float    g_negS[NROWS];            // atomically accumulated neg sums
__device__ float    g_posv[NROWS * CAPR];
__device__ int      g_pcnt[NROWS];
__device__ float    g_rowSum[NROWS];
__device__ int      g_rowCnt[NROWS];
__device__ float    g_rankS[64];
__device__ int      g_rankC[64];

// ---------------- helpers ----------------
__device__ __forceinline__ uint32_t smem_u32(const void* p) {
    return (uint32_t)__cvta_generic_to_shared(p);
}
__device__ __forceinline__ float ex2(float x) {
    float r;
    asm("ex2.approx.f32 %0, %1;" : "=f"(r) : "f"(x));
    return r;
}
__device__ __forceinline__ uint32_t fp8x4(float f0, float f1, float f2, float f3) {
    uint16_t lo, hi;
    asm("cvt.rn.satfinite.e4m3x2.f32 %0, %1, %2;" : "=h"(lo) : "f"(f1), "f"(f0));
    asm("cvt.rn.satfinite.e4m3x2.f32 %0, %1, %2;" : "=h"(hi) : "f"(f3), "f"(f2));
    return (uint32_t)lo | ((uint32_t)hi << 16);
}
// fp8 e4m3 MMA, K=32 per instruction
__device__ __forceinline__ void mmaf8(float d[4], const uint32_t a[4],
                                      const uint32_t b[2]) {
    asm volatile(
        "mma.sync.aligned.m16n8k32.row.col.f32.e4m3.e4m3.f32 "
        "{%0,%1,%2,%3}, {%4,%5,%6,%7}, {%8,%9}, {%0,%1,%2,%3};\n"
        : "+f"(d[0]), "+f"(d[1]), "+f"(d[2]), "+f"(d[3])
        : "r"(a[0]), "r"(a[1]), "r"(a[2]), "r"(a[3]), "r"(b[0]), "r"(b[1]));
}
__device__ __forceinline__ void ldsm4(uint32_t addr, uint32_t r[4]) {
    asm volatile("ldmatrix.sync.aligned.m8n8.x4.shared.b16 {%0,%1,%2,%3}, [%4];"
                 : "=r"(r[0]), "=r"(r[1]), "=r"(r[2]), "=r"(r[3]) : "r"(addr));
}
__device__ __forceinline__ void cp16(uint32_t dst, const void* src) {
    uint64_t gs;
    asm("cvta.to.global.u64 %0, %1;" : "=l"(gs) : "l"(src));
    asm volatile("cp.async.cg.shared.global [%0], [%1], 16;" :: "r"(dst), "l"(gs));
}
#define CP_COMMIT() asm volatile("cp.async.commit_group;" ::: "memory")
#define CP_WAIT0()  asm volatile("cp.async.wait_group 0;" ::: "memory")
#define CP_WAIT1()  asm volatile("cp.async.wait_group 1;" ::: "memory")

// 128x256B fp8 tile -> 256B rows with XOR-16B-chunk swizzle: chunk' = ch ^ (row&7)
__device__ __forceinline__ void cp_tile(uint32_t dstBase, int row0) {
    const char* src = (const char*)g_Z8 + (size_t)row0 * 256;
    #pragma unroll
    for (int it = 0; it < 4; it++) {
        int idx = it * NTHREADS + threadIdx.x;
        int r = idx >> 4, ch = idx & 15;
        cp16(dstBase + r * 256 + ((ch ^ (r & 7)) << 4), src + r * 256 + ch * 16);
    }
}

// ---------------- kernel 1: normalize -> e4m3 (+ zero accumulators) ----------------
__global__ void normalize_kernel(const float* __restrict__ za,
                                 const float* __restrict__ zb,
                                 const int*   __restrict__ pa,
                                 const int*   __restrict__ pb) {
    int warp = threadIdx.x >> 5;
    int lane = threadIdx.x & 31;
    int row  = blockIdx.x * 8 + warp;
    const float* src = (row < BATCH) ? (za + (size_t)row * D)
                                     : (zb + (size_t)(row - BATCH) * D);
    int k0 = lane * 4;
    float4 v0 = *(const float4*)(src + k0);
    float4 v1 = *(const float4*)(src + k0 + 128);
    float ss = v0.x*v0.x + v0.y*v0.y + v0.z*v0.z + v0.w*v0.w
             + v1.x*v1.x + v1.y*v1.y + v1.z*v1.z + v1.w*v1.w;
    #pragma unroll
    for (int off = 16; off; off >>= 1) ss += __shfl_xor_sync(0xffffffffu, ss, off);
    float inv = 1.0f / fmaxf(sqrtf(ss), 1e-8f);

    uint32_t* dst = g_Z8 + (size_t)row * 64;
    dst[lane]      = fp8x4(v0.x * inv, v0.y * inv, v0.z * inv, v0.w * inv);
    dst[32 + lane] = fp8x4(v1.x * inv, v1.y * inv, v1.z * inv, v1.w * inv);
    if (lane == 0) {
        g_pieces[row] = (row < BATCH) ? pa[row] : pb[row - BATCH];
        g_pcnt[row]   = 0;
        g_negS[row]   = 0.f;
    }
}

// ---------------- kernel 2: symmetric FP8 MMA GEMM + fused masked LSE ----------------
__global__ void __launch_bounds__(NTHREADS, 1) simlse_kernel() {
    extern __shared__ uint8_t dsm[];
    __shared__ int   s_pi[128];
    __shared__ int   s_pj[128];
    __shared__ float s_rowRed[128][8];
    __shared__ float s_colRed[128][2];

    const int tid  = threadIdx.x;
    const int warp = tid >> 5;
    const int lane = tid & 31;
    const int wm = warp >> 3;         // 0..1 (m)
    const int wn = warp & 7;          // 0..7 (n)
    const int q  = lane >> 2;         // 0..7

    const uint32_t sbase = smem_u32(dsm);
    const uint32_t bufA  = sbase;
    const uint32_t bufB0 = sbase + TILEB;
    const uint32_t bufB1 = sbase + 2 * TILEB;

    // static balanced unit assignment: 2080 = 148*14 + 8
    const int c = blockIdx.x;
    const int ustart = c * 14 + (c < 8 ? c : 8);
    const int ucount = 14 + (c < 8 ? 1 : 0);

    int ib = 0, rem = ustart;
    while (rem >= NBLK - ib) { rem -= NBLK - ib; ib++; }
    int jb = ib + rem;

    cp_tile(bufA, ib * 128);
    cp_tile(bufB0, jb * 128);
    CP_COMMIT();
    if (tid < 128) s_pi[tid] = g_pieces[ib * 128 + tid];

    // ldmatrix lane bases (rows are 256 bytes, 16 chunks of 16B)
    const uint32_t aRow = bufA + (uint32_t)(wm * 64 + (lane & 15)) * 256;
    const uint32_t bRowOff = (uint32_t)(wn * 16 + ((lane >> 4) & 1) * 8 + (lane & 7)) * 256;
    const uint32_t ax = (uint32_t)(lane >> 4);        // A base chunk (0/1)
    const uint32_t bx = (uint32_t)((lane >> 3) & 1);  // B base chunk (0/1)
    const uint32_t xr = (uint32_t)(lane & 7);

    for (int un = 0; un < ucount; un++) {
        const int par = un & 1;
        int nib = ib, njb = jb + 1;
        if (njb == NBLK) { nib = ib + 1; njb = nib; }
        const bool hasNext = (un + 1 < ucount);

        if (hasNext) {
            cp_tile(par ? bufB0 : bufB1, njb * 128);
            CP_COMMIT();
            CP_WAIT1();
        } else {
            CP_WAIT0();
        }
        __syncthreads();

        if (tid < 128) s_pj[tid] = g_pieces[jb * 128 + tid];

        int mypc[8];
        #pragma unroll
        for (int mt = 0; mt < 4; mt++)
            #pragma unroll
            for (int h = 0; h < 2; h++)
                mypc[mt * 2 + h] = s_pi[wm * 64 + mt * 16 + q + 8 * h];

        // ---- MMA: warp tile 64(m) x 16(n), K=256 fp8, 8 ks of K=32 ----
        float acc[4][2][4];
        #pragma unroll
        for (int mt = 0; mt < 4; mt++)
            #pragma unroll
            for (int nt = 0; nt < 2; nt++)
                #pragma unroll
                for (int e = 0; e < 4; e++) acc[mt][nt][e] = 0.f;

        const uint32_t bRow = (par ? bufB1 : bufB0) + bRowOff;

        uint32_t afr[2][4][4], bfr[2][2][2];
        {   // preload ks = 0
            const uint32_t aoff = ((ax ^ xr) << 4);
            const uint32_t boff = ((bx ^ xr) << 4);
            #pragma unroll
            for (int mt = 0; mt < 4; mt++)
                ldsm4(aRow + (uint32_t)mt * 4096 + aoff, afr[0][mt]);
            uint32_t r[4];
            ldsm4(bRow + boff, r);
            bfr[0][0][0] = r[0]; bfr[0][0][1] = r[1];
            bfr[0][1][0] = r[2]; bfr[0][1][1] = r[3];
        }
        #pragma unroll
        for (int ks = 0; ks < 8; ks++) {
            const int cur = ks & 1, nxt = cur ^ 1;
            if (ks < 7) {
                const uint32_t aoff = (((ax + (uint32_t)(ks + 1) * 2) ^ xr) << 4);
                const uint32_t boff = (((bx + (uint32_t)(ks + 1) * 2) ^ xr) << 4);
                #pragma unroll
                for (int mt = 0; mt < 4; mt++)
                    ldsm4(aRow + (uint32_t)mt * 4096 + aoff, afr[nxt][mt]);
                uint32_t r[4];
                ldsm4(bRow + boff, r);
                bfr[nxt][0][0] = r[0]; bfr[nxt][0][1] = r[1];
                bfr[nxt][1][0] = r[2]; bfr[nxt][1][1] = r[3];
            }
            #pragma unroll
            for (int mt = 0; mt < 4; mt++)
                #pragma unroll
                for (int nt = 0; nt < 2; nt++)
                    mmaf8(acc[mt][nt], afr[cur][mt], bfr[cur][nt]);
        }
        __syncthreads();   // all MMA smem reads done; s_pj visible

        // ---- fused epilogue: row pass + column pass ----
        const bool isDiag = (ib == jb);
        int pjc[4];
        #pragma unroll
        for (int nt = 0; nt < 2; nt++)
            #pragma unroll
            for (int cc = 0; cc < 2; cc++)
                pjc[nt * 2 + cc] = s_pj[wn * 16 + nt * 8 + (lane & 3) * 2 + cc];

        const int jgBase = jb * 128 + wn * 16 + (lane & 3) * 2;
        float colacc[4] = {0.f, 0.f, 0.f, 0.f};

        #pragma unroll
        for (int mt = 0; mt < 4; mt++)
            #pragma unroll
            for (int h = 0; h < 2; h++) {
                const int rloc = wm * 64 + mt * 16 + q + 8 * h;
                const int ig = ib * 128 + rloc;
                const int myp = mypc[mt * 2 + h];
                float na = 0.f;
                #pragma unroll
                for (int nt = 0; nt < 2; nt++)
                    #pragma unroll
                    for (int cc = 0; cc < 2; cc++) {
                        float dot = acc[mt][nt][h * 2 + cc];
                        float e = ex2(fmaf(dot, C2EXP, -C2EXP));
                        bool same = (pjc[nt * 2 + cc] == myp);
                        na += same ? 0.f : e;
                        colacc[nt * 2 + cc] += same ? 0.f : e;
                        if (same) {
                            int jg = jgBase + nt * 8 + cc;
                            if (!isDiag || jg != ig) {
                                float sim = dot * INV_T;
                                int sl = atomicAdd(&g_pcnt[ig], 1);
                                if (sl < CAPR) g_posv[ig * CAPR + sl] = sim;
                                if (!isDiag) {
                                    int sl2 = atomicAdd(&g_pcnt[jg], 1);
                                    if (sl2 < CAPR) g_posv[jg * CAPR + sl2] = sim;
                                }
                            }
                        }
                    }
                na += __shfl_xor_sync(0xffffffffu, na, 1);
                na += __shfl_xor_sync(0xffffffffu, na, 2);
                if ((lane & 3) == 0) s_rowRed[rloc][wn] = na;
            }

        if (!isDiag) {
            #pragma unroll
            for (int idx = 0; idx < 4; idx++) {
                colacc[idx] += __shfl_xor_sync(0xffffffffu, colacc[idx], 4);
                colacc[idx] += __shfl_xor_sync(0xffffffffu, colacc[idx], 8);
                colacc[idx] += __shfl_xor_sync(0xffffffffu, colacc[idx], 16);
            }
            if (lane < 4) {
                #pragma unroll
                for (int nt = 0; nt < 2; nt++)
                    #pragma unroll
                    for (int cc = 0; cc < 2; cc++)
                        s_colRed[wn * 16 + nt * 8 + lane * 2 + cc][wm] =
                            colacc[nt * 2 + cc];
            }
        }
        __syncthreads();

        if (tid < 128) {
            float v = 0.f;
            #pragma unroll
            for (int k = 0; k < 8; k++) v += s_rowRed[tid][k];
            atomicAdd(&g_negS[ib * 128 + tid], v);
            if (!isDiag) {
                float w = s_colRed[tid][0] + s_colRed[tid][1];
                atomicAdd(&g_negS[jb * 128 + tid], w);
            }
        }

        // A switch for next unit
        if (hasNext && nib != ib) {
            cp_tile(bufA, nib * 128);
            CP_COMMIT();
            if (tid < 128) s_pi[tid] = g_pieces[nib * 128 + tid];
        }
        ib = nib; jb = njb;
    }
}

// ---------------- kernel 3: ranking loss partials ----------------
__global__ void ranking_kernel(const float* __restrict__ logits,
                               const float* __restrict__ la,
                               const float* __restrict__ lb) {
    __shared__ float ssum[256];
    __shared__ int   scnt[256];
    int tid = threadIdx.x;
    float sum = 0.f; int cnt = 0;
    for (int i = blockIdx.x * 256 + tid; i < BATCH * NDIMS; i += 64 * 256) {
        float diff = la[i] - lb[i];
        if (fabsf(diff) >= 0.05f) {
            float t = (diff > 0.f ? 0.9f : 0.f) + 0.05f;
            float l = logits[i];
            sum += fmaxf(l, 0.f) - l * t + log1pf(__expf(-fabsf(l)));
            cnt++;
        }
    }
    ssum[tid] = sum; scnt[tid] = cnt;
    __syncthreads();
    for (int o = 128; o; o >>= 1) {
        if (tid < o) { ssum[tid] += ssum[tid + o]; scnt[tid] += scnt[tid + o]; }
        __syncthreads();
    }
    if (tid == 0) { g_rankS[blockIdx.x] = ssum[0]; g_rankC[blockIdx.x] = scnt[0]; }
}

// ---------------- kernel 4: per-row merge (warp per row) ----------------
__global__ void final_row_kernel() {
    const int warp = threadIdx.x >> 5;
    const int lane = threadIdx.x & 31;
    const int i = blockIdx.x * 8 + warp;

    float S = __shfl_sync(0xffffffffu, (lane == 0) ? g_negS[i] : 0.f, 0);
    int n = g_pcnt[i];
    if (n > CAPR) n = CAPR;
    float sum = 0.f;
    int cnt = 0;
    if (S > 0.f) {
        float nl = INV_T + logf(S);
        cnt = n;
        for (int s = lane; s < n; s += 32) {
            float d = nl - g_posv[i * CAPR + s];
            sum += (d > 0.f) ? (d + log1pf(__expf(-d))) : log1pf(__expf(d));
        }
    }
    #pragma unroll
    for (int o = 16; o; o >>= 1) sum += __shfl_xor_sync(0xffffffffu, sum, o);
    if (lane == 0) { g_rowSum[i] = sum; g_rowCnt[i] = cnt; }
}

// ---------------- kernel 5: final deterministic reduce ----------------
__global__ void final_kernel(float* __restrict__ out, int out_size) {
    __shared__ float ssum[256];
    __shared__ int   scnt[256];
    int tid = threadIdx.x;
    float sum = 0.f; int cnt = 0;
    for (int i = tid; i < NROWS; i += 256) { sum += g_rowSum[i]; cnt += g_rowCnt[i]; }
    ssum[tid] = sum; scnt[tid] = cnt;
    __syncthreads();
    for (int o = 128; o; o >>= 1) {
        if (tid < o) { ssum[tid] += ssum[tid + o]; scnt[tid] += scnt[tid + o]; }
        __syncthreads();
    }
    if (tid == 0) {
        float rs = 0.f; int rc = 0;
        for (int b = 0; b < 64; b++) { rs += g_rankS[b]; rc += g_rankC[b]; }
        float lcon  = (scnt[0] > 0) ? (ssum[0] / (float)scnt[0]) : 0.f;
        float lrank = (rc > 0) ? (rs / (float)rc) : 0.f;
        out[0] = lrank + 0.3f * lcon;
        if (out_size > 1) out[1] = lrank;
        if (out_size > 2) out[2] = lcon;
    }
}

// ---------------- launch ----------------
extern "C" void kernel_launch(void* const* d_in, const int* in_sizes, int n_in,
                              void* d_out, int out_size) {
    const float* za     = (const float*)d_in[0];
    const float* zb     = (const float*)d_in[1];
    const float* logits = (const float*)d_in[2];
    const float* la     = (const float*)d_in[3];
    const float* lb     = (const float*)d_in[4];
    const int*   pa     = (const int*)d_in[5];
    const int*   pb     = (const int*)d_in[6];
    float* out = (float*)d_out;

    const int dynSmem = 3 * TILEB;   // A + B0 + B1 = 98304 bytes
    cudaFuncSetAttribute(simlse_kernel,
                         cudaFuncAttributeMaxDynamicSharedMemorySize, dynSmem);

    normalize_kernel<<<NROWS / 8, 256>>>(za, zb, pa, pb);
    ranking_kernel<<<64, 256>>>(logits, la, lb);
    simlse_kernel<<<NCTA, NTHREADS, dynSmem>>>();
    final_row_kernel<<<NROWS / 8, 256>>>();
    final_kernel<<<1, 256>>>(out, out_size);
}

// round 10
// speedup vs baseline: 1.0432x; 1.0432x over previous
#include <cuda_runtime.h>
#include <cuda_bf16.h>
#include <cstdint>

// ---------------- problem constants ----------------
#define BATCH    4096
#define NDIMS    19
#define D        256
#define NROWS    8192
#define NBLK     64                    // 64 row-blocks of 128
#define NCTA     148
#define INV_T    14.285714285714286f
#define C2EXP    (14.285714285714286f * 1.4426950408889634f)   // INV_T * log2(e)
#define CAPR     32                    // positive slots per row
#define NTHREADS 512
#define TILEB    32768                 // 128 rows x 256 bytes (fp8)

// ---------------- device scratch ----------------
__device__ uint32_t g_Z8[NROWS * 64];         // normalized e4m3 rows (4 per u32)
__device__ int      g_pieces[NROWS];
__device__ float    g_negS[NROWS];            // atomically accumulated neg sums
__device__ float    g_posv[NROWS * CAPR];
__device__ int      g_pcnt[NROWS];
__device__ float    g_rowSum[NROWS];
__device__ int      g_rowCnt[NROWS];
__device__ float    g_rankS[64];
__device__ int      g_rankC[64];

// ---------------- helpers ----------------
__device__ __forceinline__ uint32_t smem_u32(const void* p) {
    return (uint32_t)__cvta_generic_to_shared(p);
}
__device__ __forceinline__ float ex2(float x) {
    float r;
    asm("ex2.approx.f32 %0, %1;" : "=f"(r) : "f"(x));
    return r;
}
__device__ __forceinline__ uint32_t fp8x4(float f0, float f1, float f2, float f3) {
    uint16_t lo, hi;
    asm("cvt.rn.satfinite.e4m3x2.f32 %0, %1, %2;" : "=h"(lo) : "f"(f1), "f"(f0));
    asm("cvt.rn.satfinite.e4m3x2.f32 %0, %1, %2;" : "=h"(hi) : "f"(f3), "f"(f2));
    return (uint32_t)lo | ((uint32_t)hi << 16);
}
// fp8 e4m3 MMA, K=32 per instruction
__device__ __forceinline__ void mmaf8(float d[4], const uint32_t a[4],
                                      const uint32_t b[2]) {
    asm volatile(
        "mma.sync.aligned.m16n8k32.row.col.f32.e4m3.e4m3.f32 "
        "{%0,%1,%2,%3}, {%4,%5,%6,%7}, {%8,%9}, {%0,%1,%2,%3};\n"
        : "+f"(d[0]), "+f"(d[1]), "+f"(d[2]), "+f"(d[3])
        : "r"(a[0]), "r"(a[1]), "r"(a[2]), "r"(a[3]), "r"(b[0]), "r"(b[1]));
}
__device__ __forceinline__ void ldsm4(uint32_t addr, uint32_t r[4]) {
    asm volatile("ldmatrix.sync.aligned.m8n8.x4.shared.b16 {%0,%1,%2,%3}, [%4];"
                 : "=r"(r[0]), "=r"(r[1]), "=r"(r[2]), "=r"(r[3]) : "r"(addr));
}
__device__ __forceinline__ void cp16(uint32_t dst, const void* src) {
    uint64_t gs;
    asm("cvta.to.global.u64 %0, %1;" : "=l"(gs) : "l"(src));
    asm volatile("cp.async.cg.shared.global [%0], [%1], 16;" :: "r"(dst), "l"(gs));
}
#define CP_COMMIT() asm volatile("cp.async.commit_group;" ::: "memory")
#define CP_WAIT0()  asm volatile("cp.async.wait_group 0;" ::: "memory")
#define CP_WAIT1()  asm volatile("cp.async.wait_group 1;" ::: "memory")

// 128x256B fp8 tile -> 256B rows with XOR-16B-chunk swizzle: chunk' = ch ^ (row&7)
__device__ __forceinline__ void cp_tile(uint32_t dstBase, int row0) {
    const char* src = (const char*)g_Z8 + (size_t)row0 * 256;
    #pragma unroll
    for (int it = 0; it < 4; it++) {
        int idx = it * NTHREADS + threadIdx.x;
        int r = idx >> 4, ch = idx & 15;
        cp16(dstBase + r * 256 + ((ch ^ (r & 7)) << 4), src + r * 256 + ch * 16);
    }
}

// ---------------- kernel 1: normalize -> e4m3 (+ zero accumulators) ----------------
__global__ void normalize_kernel(const float* __restrict__ za,
                                 const float* __restrict__ zb,
                                 const int*   __restrict__ pa,
                                 const int*   __restrict__ pb) {
    int warp = threadIdx.x >> 5;
    int lane = threadIdx.x & 31;
    int row  = blockIdx.x * 8 + warp;
    const float* src = (row < BATCH) ? (za + (size_t)row * D)
                                     : (zb + (size_t)(row - BATCH) * D);
    int k0 = lane * 4;
    float4 v0 = *(const float4*)(src + k0);
    float4 v1 = *(const float4*)(src + k0 + 128);
    float ss = v0.x*v0.x + v0.y*v0.y + v0.z*v0.z + v0.w*v0.w
             + v1.x*v1.x + v1.y*v1.y + v1.z*v1.z + v1.w*v1.w;
    #pragma unroll
    for (int off = 16; off; off >>= 1) ss += __shfl_xor_sync(0xffffffffu, ss, off);
    float inv = 1.0f / fmaxf(sqrtf(ss), 1e-8f);

    uint32_t* dst = g_Z8 + (size_t)row * 64;
    dst[lane]      = fp8x4(v0.x * inv, v0.y * inv, v0.z * inv, v0.w * inv);
    dst[32 + lane] = fp8x4(v1.x * inv, v1.y * inv, v1.z * inv, v1.w * inv);
    if (lane == 0) {
        g_pieces[row] = (row < BATCH) ? pa[row] : pb[row - BATCH];
        g_pcnt[row]   = 0;
        g_negS[row]   = 0.f;
    }
}

// ---------------- kernel 2: symmetric FP8 MMA GEMM + fused masked LSE ----------------
__global__ void __launch_bounds__(NTHREADS, 1) simlse_kernel() {
    extern __shared__ uint8_t dsm[];
    __shared__ int   s_pi[128];
    __shared__ int   s_pj[128];
    __shared__ float s_rowRed[128][8];
    __shared__ float s_colRed[128][2];

    const int tid  = threadIdx.x;
    const int warp = tid >> 5;
    const int lane = tid & 31;
    const int wm = warp >> 3;         // 0..1 (m)
    const int wn = warp & 7;          // 0..7 (n)
    const int q  = lane >> 2;         // 0..7

    const uint32_t sbase = smem_u32(dsm);
    const uint32_t bufA  = sbase;
    const uint32_t bufB0 = sbase + TILEB;
    const uint32_t bufB1 = sbase + 2 * TILEB;

    // static balanced unit assignment: 2080 = 148*14 + 8
    const int c = blockIdx.x;
    const int ustart = c * 14 + (c < 8 ? c : 8);
    const int ucount = 14 + (c < 8 ? 1 : 0);

    int ib = 0, rem = ustart;
    while (rem >= NBLK - ib) { rem -= NBLK - ib; ib++; }
    int jb = ib + rem;

    cp_tile(bufA, ib * 128);
    cp_tile(bufB0, jb * 128);
    CP_COMMIT();
    if (tid < 128) s_pi[tid] = g_pieces[ib * 128 + tid];

    // ldmatrix lane bases (rows are 256 bytes, 16 chunks of 16B)
    const uint32_t aRow = bufA + (uint32_t)(wm * 64 + (lane & 15)) * 256;
    const uint32_t bRowOff = (uint32_t)(wn * 16 + ((lane >> 4) & 1) * 8 + (lane & 7)) * 256;
    const uint32_t ax = (uint32_t)(lane >> 4);        // A base chunk (0/1)
    const uint32_t bx = (uint32_t)((lane >> 3) & 1);  // B base chunk (0/1)
    const uint32_t xr = (uint32_t)(lane & 7);

    for (int un = 0; un < ucount; un++) {
        const int par = un & 1;
        int nib = ib, njb = jb + 1;
        if (njb == NBLK) { nib = ib + 1; njb = nib; }
        const bool hasNext = (un + 1 < ucount);

        if (hasNext) {
            cp_tile(par ? bufB0 : bufB1, njb * 128);
            CP_COMMIT();
            CP_WAIT1();
        } else {
            CP_WAIT0();
        }
        __syncthreads();

        if (tid < 128) s_pj[tid] = g_pieces[jb * 128 + tid];

        int mypc[8];
        #pragma unroll
        for (int mt = 0; mt < 4; mt++)
            #pragma unroll
            for (int h = 0; h < 2; h++)
                mypc[mt * 2 + h] = s_pi[wm * 64 + mt * 16 + q + 8 * h];

        // ---- MMA: warp tile 64(m) x 16(n), K=256 fp8, 8 ks of K=32 ----
        float acc[4][2][4];
        #pragma unroll
        for (int mt = 0; mt < 4; mt++)
            #pragma unroll
            for (int nt = 0; nt < 2; nt++)
                #pragma unroll
                for (int e = 0; e < 4; e++) acc[mt][nt][e] = 0.f;

        const uint32_t bRow = (par ? bufB1 : bufB0) + bRowOff;

        uint32_t afr[2][4][4], bfr[2][2][2];
        {   // preload ks = 0
            const uint32_t aoff = ((ax ^ xr) << 4);
            const uint32_t boff = ((bx ^ xr) << 4);
            #pragma unroll
            for (int mt = 0; mt < 4; mt++)
                ldsm4(aRow + (uint32_t)mt * 4096 + aoff, afr[0][mt]);
            uint32_t r[4];
            ldsm4(bRow + boff, r);
            bfr[0][0][0] = r[0]; bfr[0][0][1] = r[1];
            bfr[0][1][0] = r[2]; bfr[0][1][1] = r[3];
        }
        #pragma unroll
        for (int ks = 0; ks < 8; ks++) {
            const int cur = ks & 1, nxt = cur ^ 1;
            if (ks < 7) {
                const uint32_t aoff = (((ax + (uint32_t)(ks + 1) * 2) ^ xr) << 4);
                const uint32_t boff = (((bx + (uint32_t)(ks + 1) * 2) ^ xr) << 4);
                #pragma unroll
                for (int mt = 0; mt < 4; mt++)
                    ldsm4(aRow + (uint32_t)mt * 4096 + aoff, afr[nxt][mt]);
                uint32_t r[4];
                ldsm4(bRow + boff, r);
                bfr[nxt][0][0] = r[0]; bfr[nxt][0][1] = r[1];
                bfr[nxt][1][0] = r[2]; bfr[nxt][1][1] = r[3];
            }
            #pragma unroll
            for (int mt = 0; mt < 4; mt++)
                #pragma unroll
                for (int nt = 0; nt < 2; nt++)
                    mmaf8(acc[mt][nt], afr[cur][mt], bfr[cur][nt]);
        }
        __syncthreads();   // all MMA smem reads done; s_pj visible

        // ---- fused epilogue: row pass + column pass ----
        const bool isDiag = (ib == jb);
        int pjc[4];
        #pragma unroll
        for (int nt = 0; nt < 2; nt++)
            #pragma unroll
            for (int cc = 0; cc < 2; cc++)
                pjc[nt * 2 + cc] = s_pj[wn * 16 + nt * 8 + (lane & 3) * 2 + cc];

        const int jgBase = jb * 128 + wn * 16 + (lane & 3) * 2;
        float colacc[4] = {0.f, 0.f, 0.f, 0.f};

        #pragma unroll
        for (int mt = 0; mt < 4; mt++)
            #pragma unroll
            for (int h = 0; h < 2; h++) {
                const int rloc = wm * 64 + mt * 16 + q + 8 * h;
                const int ig = ib * 128 + rloc;
                const int myp = mypc[mt * 2 + h];
                float na = 0.f;
                #pragma unroll
                for (int nt = 0; nt < 2; nt++)
                    #pragma unroll
                    for (int cc = 0; cc < 2; cc++) {
                        float dot = acc[mt][nt][h * 2 + cc];
                        float e = ex2(fmaf(dot, C2EXP, -C2EXP));
                        bool same = (pjc[nt * 2 + cc] == myp);
                        na += same ? 0.f : e;
                        colacc[nt * 2 + cc] += same ? 0.f : e;
                        if (same) {
                            int jg = jgBase + nt * 8 + cc;
                            if (!isDiag || jg != ig) {
                                float sim = dot * INV_T;
                                int sl = atomicAdd(&g_pcnt[ig], 1);
                                if (sl < CAPR) g_posv[ig * CAPR + sl] = sim;
                                if (!isDiag) {
                                    int sl2 = atomicAdd(&g_pcnt[jg], 1);
                                    if (sl2 < CAPR) g_posv[jg * CAPR + sl2] = sim;
                                }
                            }
                        }
                    }
                na += __shfl_xor_sync(0xffffffffu, na, 1);
                na += __shfl_xor_sync(0xffffffffu, na, 2);
                if ((lane & 3) == 0) s_rowRed[rloc][wn] = na;
            }

        if (!isDiag) {
            #pragma unroll
            for (int idx = 0; idx < 4; idx++) {
                colacc[idx] += __shfl_xor_sync(0xffffffffu, colacc[idx], 4);
                colacc[idx] += __shfl_xor_sync(0xffffffffu, colacc[idx], 8);
                colacc[idx] += __shfl_xor_sync(0xffffffffu, colacc[idx], 16);
            }
            if (lane < 4) {
                #pragma unroll
                for (int nt = 0; nt < 2; nt++)
                    #pragma unroll
                    for (int cc = 0; cc < 2; cc++)
                        s_colRed[wn * 16 + nt * 8 + lane * 2 + cc][wm] =
                            colacc[nt * 2 + cc];
            }
        }
        __syncthreads();

        if (tid < 128) {
            float v = 0.f;
            #pragma unroll
            for (int k = 0; k < 8; k++) v += s_rowRed[tid][k];
            atomicAdd(&g_negS[ib * 128 + tid], v);
            if (!isDiag) {
                float w = s_colRed[tid][0] + s_colRed[tid][1];
                atomicAdd(&g_negS[jb * 128 + tid], w);
            }
        }

        // A switch for next unit
        if (hasNext && nib != ib) {
            cp_tile(bufA, nib * 128);
            CP_COMMIT();
            if (tid < 128) s_pi[tid] = g_pieces[nib * 128 + tid];
        }
        ib = nib; jb = njb;
    }
}

// ---------------- kernel 3: ranking loss partials ----------------
__global__ void ranking_kernel(const float* __restrict__ logits,
                               const float* __restrict__ la,
                               const float* __restrict__ lb) {
    __shared__ float ssum[256];
    __shared__ int   scnt[256];
    int tid = threadIdx.x;
    float sum = 0.f; int cnt = 0;
    for (int i = blockIdx.x * 256 + tid; i < BATCH * NDIMS; i += 64 * 256) {
        float diff = la[i] - lb[i];
        if (fabsf(diff) >= 0.05f) {
            float t = (diff > 0.f ? 0.9f : 0.f) + 0.05f;
            float l = logits[i];
            sum += fmaxf(l, 0.f) - l * t + log1pf(__expf(-fabsf(l)));
            cnt++;
        }
    }
    ssum[tid] = sum; scnt[tid] = cnt;
    __syncthreads();
    for (int o = 128; o; o >>= 1) {
        if (tid < o) { ssum[tid] += ssum[tid + o]; scnt[tid] += scnt[tid + o]; }
        __syncthreads();
    }
    if (tid == 0) { g_rankS[blockIdx.x] = ssum[0]; g_rankC[blockIdx.x] = scnt[0]; }
}

// ---------------- kernel 4: per-row merge (warp per row) ----------------
__global__ void final_row_kernel() {
    const int warp = threadIdx.x >> 5;
    const int lane = threadIdx.x & 31;
    const int i = blockIdx.x * 8 + warp;

    float S = __shfl_sync(0xffffffffu, (lane == 0) ? g_negS[i] : 0.f, 0);
    int n = g_pcnt[i];
    if (n > CAPR) n = CAPR;
    float sum = 0.f;
    int cnt = 0;
    if (S > 0.f) {
        float nl = INV_T + logf(S);
        cnt = n;
        for (int s = lane; s < n; s += 32) {
            float d = nl - g_posv[i * CAPR + s];
            sum += (d > 0.f) ? (d + log1pf(__expf(-d))) : log1pf(__expf(d));
        }
    }
    #pragma unroll
    for (int o = 16; o; o >>= 1) sum += __shfl_xor_sync(0xffffffffu, sum, o);
    if (lane == 0) { g_rowSum[i] = sum; g_rowCnt[i] = cnt; }
}

// ---------------- kernel 5: final deterministic reduce ----------------
__global__ void final_kernel(float* __restrict__ out, int out_size) {
    __shared__ float ssum[256];
    __shared__ int   scnt[256];
    int tid = threadIdx.x;
    float sum = 0.f; int cnt = 0;
    for (int i = tid; i < NROWS; i += 256) { sum += g_rowSum[i]; cnt += g_rowCnt[i]; }
    ssum[tid] = sum; scnt[tid] = cnt;
    __syncthreads();
    for (int o = 128; o; o >>= 1) {
        if (tid < o) { ssum[tid] += ssum[tid + o]; scnt[tid] += scnt[tid + o]; }
        __syncthreads();
    }
    if (tid == 0) {
        float rs = 0.f; int rc = 0;
        for (int b = 0; b < 64; b++) { rs += g_rankS[b]; rc += g_rankC[b]; }
        float lcon  = (scnt[0] > 0) ? (ssum[0] / (float)scnt[0]) : 0.f;
        float lrank = (rc > 0) ? (rs / (float)rc) : 0.f;
        out[0] = lrank + 0.3f * lcon;
        if (out_size > 1) out[1] = lrank;
        if (out_size > 2) out[2] = lcon;
    }
}

// ---------------- launch ----------------
extern "C" void kernel_launch(void* const* d_in, const int* in_sizes, int n_in,
                              void* d_out, int out_size) {
    const float* za     = (const float*)d_in[0];
    const float* zb     = (const float*)d_in[1];
    const float* logits = (const float*)d_in[2];
    const float* la     = (const float*)d_in[3];
    const float* lb     = (const float*)d_in[4];
    const int*   pa     = (const int*)d_in[5];
    const int*   pb     = (const int*)d_in[6];
    float* out = (float*)d_out;

    const int dynSmem = 3 * TILEB;   // A + B0 + B1 = 98304 bytes
    cudaFuncSetAttribute(simlse_kernel,
                         cudaFuncAttributeMaxDynamicSharedMemorySize, dynSmem);

    normalize_kernel<<<NROWS / 8, 256>>>(za, zb, pa, pb);
    ranking_kernel<<<64, 256>>>(logits, la, lb);
    simlse_kernel<<<NCTA, NTHREADS, dynSmem>>>();
    final_row_kernel<<<NROWS / 8, 256>>>();
    final_kernel<<<1, 256>>>(out, out_size);
}

// round 11
// speedup vs baseline: 1.0549x; 1.0112x over previous
#include <cuda_runtime.h>
#include <cuda_bf16.h>
#include <cstdint>

// ---------------- problem constants ----------------
#define BATCH    4096
#define NDIMS    19
#define D        256
#define NROWS    8192
#define NBLK     64                    // 64 row-blocks of 128
#define NCTA     148
#define INV_T    14.285714285714286f
#define C2EXP    (14.285714285714286f * 1.4426950408889634f)   // INV_T * log2(e)
#define CAPR     32                    // positive slots per row
#define NTHREADS 512
#define TILEB    32768                 // 128 rows x 256 bytes (fp8)

// ---------------- device scratch ----------------
__device__ uint32_t g_Z8[NROWS * 64];         // normalized e4m3 rows (4 per u32)
__device__ int      g_pieces[NROWS];
__device__ float    g_negS[NROWS];            // atomically accumulated neg sums
__device__ float    g_posv[NROWS * CAPR];
__device__ int      g_pcnt[NROWS];
__device__ float    g_rowSum[NROWS];
__device__ int      g_rowCnt[NROWS];
__device__ float    g_rankS[64];
__device__ int      g_rankC[64];

// ---------------- helpers ----------------
__device__ __forceinline__ uint32_t smem_u32(const void* p) {
    return (uint32_t)__cvta_generic_to_shared(p);
}
__device__ __forceinline__ float ex2(float x) {
    float r;
    asm("ex2.approx.f32 %0, %1;" : "=f"(r) : "f"(x));
    return r;
}
__device__ __forceinline__ uint32_t fp8x4(float f0, float f1, float f2, float f3) {
    uint16_t lo, hi;
    asm("cvt.rn.satfinite.e4m3x2.f32 %0, %1, %2;" : "=h"(lo) : "f"(f1), "f"(f0));
    asm("cvt.rn.satfinite.e4m3x2.f32 %0, %1, %2;" : "=h"(hi) : "f"(f3), "f"(f2));
    return (uint32_t)lo | ((uint32_t)hi << 16);
}
// fp8 e4m3 MMA, K=32 per instruction
__device__ __forceinline__ void mmaf8(float d[4], const uint32_t a[4],
                                      const uint32_t b[2]) {
    asm volatile(
        "mma.sync.aligned.m16n8k32.row.col.f32.e4m3.e4m3.f32 "
        "{%0,%1,%2,%3}, {%4,%5,%6,%7}, {%8,%9}, {%0,%1,%2,%3};\n"
        : "+f"(d[0]), "+f"(d[1]), "+f"(d[2]), "+f"(d[3])
        : "r"(a[0]), "r"(a[1]), "r"(a[2]), "r"(a[3]), "r"(b[0]), "r"(b[1]));
}
__device__ __forceinline__ void ldsm4(uint32_t addr, uint32_t r[4]) {
    asm volatile("ldmatrix.sync.aligned.m8n8.x4.shared.b16 {%0,%1,%2,%3}, [%4];"
                 : "=r"(r[0]), "=r"(r[1]), "=r"(r[2]), "=r"(r[3]) : "r"(addr));
}
__device__ __forceinline__ void cp16(uint32_t dst, const void* src) {
    uint64_t gs;
    asm("cvta.to.global.u64 %0, %1;" : "=l"(gs) : "l"(src));
    asm volatile("cp.async.cg.shared.global [%0], [%1], 16;" :: "r"(dst), "l"(gs));
}
#define CP_COMMIT() asm volatile("cp.async.commit_group;" ::: "memory")
#define CP_WAIT0()  asm volatile("cp.async.wait_group 0;" ::: "memory")
#define CP_WAIT1()  asm volatile("cp.async.wait_group 1;" ::: "memory")

// 128x256B fp8 tile -> 256B rows with XOR-16B-chunk swizzle: chunk' = ch ^ (row&7)
__device__ __forceinline__ void cp_tile(uint32_t dstBase, int row0) {
    const char* src = (const char*)g_Z8 + (size_t)row0 * 256;
    #pragma unroll
    for (int it = 0; it < 4; it++) {
        int idx = it * NTHREADS + threadIdx.x;
        int r = idx >> 4, ch = idx & 15;
        cp16(dstBase + r * 256 + ((ch ^ (r & 7)) << 4), src + r * 256 + ch * 16);
    }
}

// ---------------- kernel 1: normalize -> e4m3 (+ zero accumulators) ----------------
__global__ void normalize_kernel(const float* __restrict__ za,
                                 const float* __restrict__ zb,
                                 const int*   __restrict__ pa,
                                 const int*   __restrict__ pb) {
    int warp = threadIdx.x >> 5;
    int lane = threadIdx.x & 31;
    int row  = blockIdx.x * 8 + warp;
    const float* src = (row < BATCH) ? (za + (size_t)row * D)
                                     : (zb + (size_t)(row - BATCH) * D);
    int k0 = lane * 4;
    float4 v0 = *(const float4*)(src + k0);
    float4 v1 = *(const float4*)(src + k0 + 128);
    float ss = v0.x*v0.x + v0.y*v0.y + v0.z*v0.z + v0.w*v0.w
             + v1.x*v1.x + v1.y*v1.y + v1.z*v1.z + v1.w*v1.w;
    #pragma unroll
    for (int off = 16; off; off >>= 1) ss += __shfl_xor_sync(0xffffffffu, ss, off);
    float inv = 1.0f / fmaxf(sqrtf(ss), 1e-8f);

    uint32_t* dst = g_Z8 + (size_t)row * 64;
    dst[lane]      = fp8x4(v0.x * inv, v0.y * inv, v0.z * inv, v0.w * inv);
    dst[32 + lane] = fp8x4(v1.x * inv, v1.y * inv, v1.z * inv, v1.w * inv);
    if (lane == 0) {
        g_pieces[row] = (row < BATCH) ? pa[row] : pb[row - BATCH];
        g_pcnt[row]   = 0;
        g_negS[row]   = 0.f;
    }
}

// ---------------- kernel 2: symmetric FP8 MMA GEMM + fused masked LSE ----------------
__global__ void __launch_bounds__(NTHREADS, 1) simlse_kernel() {
    extern __shared__ uint8_t dsm[];
    __shared__ int   s_pi[128];
    __shared__ int   s_pj[128];
    __shared__ float s_rowRed[128][8];
    __shared__ float s_colRed[128][2];

    const int tid  = threadIdx.x;
    const int warp = tid >> 5;
    const int lane = tid & 31;
    const int wm = warp >> 3;         // 0..1 (m)
    const int wn = warp & 7;          // 0..7 (n)
    const int q  = lane >> 2;         // 0..7

    const uint32_t sbase = smem_u32(dsm);
    const uint32_t bufA  = sbase;
    const uint32_t bufB0 = sbase + TILEB;
    const uint32_t bufB1 = sbase + 2 * TILEB;

    // static balanced unit assignment: 2080 = 148*14 + 8
    const int c = blockIdx.x;
    const int ustart = c * 14 + (c < 8 ? c : 8);
    const int ucount = 14 + (c < 8 ? 1 : 0);

    int ib = 0, rem = ustart;
    while (rem >= NBLK - ib) { rem -= NBLK - ib; ib++; }
    int jb = ib + rem;

    cp_tile(bufA, ib * 128);
    cp_tile(bufB0, jb * 128);
    CP_COMMIT();
    if (tid < 128) s_pi[tid] = g_pieces[ib * 128 + tid];

    // ldmatrix lane bases (rows are 256 bytes, 16 chunks of 16B)
    const uint32_t aRow = bufA + (uint32_t)(wm * 64 + (lane & 15)) * 256;
    const uint32_t bRowOff = (uint32_t)(wn * 16 + ((lane >> 4) & 1) * 8 + (lane & 7)) * 256;
    const uint32_t ax = (uint32_t)(lane >> 4);        // A base chunk (0/1)
    const uint32_t bx = (uint32_t)((lane >> 3) & 1);  // B base chunk (0/1)
    const uint32_t xr = (uint32_t)(lane & 7);

    for (int un = 0; un < ucount; un++) {
        const int par = un & 1;
        int nib = ib, njb = jb + 1;
        if (njb == NBLK) { nib = ib + 1; njb = nib; }
        const bool hasNext = (un + 1 < ucount);

        if (hasNext) {
            cp_tile(par ? bufB0 : bufB1, njb * 128);
            CP_COMMIT();
            CP_WAIT1();
        } else {
            CP_WAIT0();
        }
        __syncthreads();

        if (tid < 128) s_pj[tid] = g_pieces[jb * 128 + tid];

        int mypc[8];
        #pragma unroll
        for (int mt = 0; mt < 4; mt++)
            #pragma unroll
            for (int h = 0; h < 2; h++)
                mypc[mt * 2 + h] = s_pi[wm * 64 + mt * 16 + q + 8 * h];

        // ---- MMA: warp tile 64(m) x 16(n), K=256 fp8, 8 ks of K=32 ----
        float acc[4][2][4];
        #pragma unroll
        for (int mt = 0; mt < 4; mt++)
            #pragma unroll
            for (int nt = 0; nt < 2; nt++)
                #pragma unroll
                for (int e = 0; e < 4; e++) acc[mt][nt][e] = 0.f;

        const uint32_t bRow = (par ? bufB1 : bufB0) + bRowOff;

        uint32_t afr[2][4][4], bfr[2][2][2];
        {   // preload ks = 0
            const uint32_t aoff = ((ax ^ xr) << 4);
            const uint32_t boff = ((bx ^ xr) << 4);
            #pragma unroll
            for (int mt = 0; mt < 4; mt++)
                ldsm4(aRow + (uint32_t)mt * 4096 + aoff, afr[0][mt]);
            uint32_t r[4];
            ldsm4(bRow + boff, r);
            bfr[0][0][0] = r[0]; bfr[0][0][1] = r[1];
            bfr[0][1][0] = r[2]; bfr[0][1][1] = r[3];
        }
        #pragma unroll
        for (int ks = 0; ks < 8; ks++) {
            const int cur = ks & 1, nxt = cur ^ 1;
            if (ks < 7) {
                const uint32_t aoff = (((ax + (uint32_t)(ks + 1) * 2) ^ xr) << 4);
                const uint32_t boff = (((bx + (uint32_t)(ks + 1) * 2) ^ xr) << 4);
                #pragma unroll
                for (int mt = 0; mt < 4; mt++)
                    ldsm4(aRow + (uint32_t)mt * 4096 + aoff, afr[nxt][mt]);
                uint32_t r[4];
                ldsm4(bRow + boff, r);
                bfr[nxt][0][0] = r[0]; bfr[nxt][0][1] = r[1];
                bfr[nxt][1][0] = r[2]; bfr[nxt][1][1] = r[3];
            }
            #pragma unroll
            for (int mt = 0; mt < 4; mt++)
                #pragma unroll
                for (int nt = 0; nt < 2; nt++)
                    mmaf8(acc[mt][nt], afr[cur][mt], bfr[cur][nt]);
        }
        __syncthreads();   // all MMA smem reads done; s_pj visible

        // ---- fused epilogue: row pass + column pass ----
        const bool isDiag = (ib == jb);
        int pjc[4];
        #pragma unroll
        for (int nt = 0; nt < 2; nt++)
            #pragma unroll
            for (int cc = 0; cc < 2; cc++)
                pjc[nt * 2 + cc] = s_pj[wn * 16 + nt * 8 + (lane & 3) * 2 + cc];

        const int jgBase = jb * 128 + wn * 16 + (lane & 3) * 2;
        float colacc[4] = {0.f, 0.f, 0.f, 0.f};

        #pragma unroll
        for (int mt = 0; mt < 4; mt++)
            #pragma unroll
            for (int h = 0; h < 2; h++) {
                const int rloc = wm * 64 + mt * 16 + q + 8 * h;
                const int ig = ib * 128 + rloc;
                const int myp = mypc[mt * 2 + h];
                float na = 0.f;
                #pragma unroll
                for (int nt = 0; nt < 2; nt++)
                    #pragma unroll
                    for (int cc = 0; cc < 2; cc++) {
                        float dot = acc[mt][nt][h * 2 + cc];
                        float e = ex2(fmaf(dot, C2EXP, -C2EXP));
                        bool same = (pjc[nt * 2 + cc] == myp);
                        na += same ? 0.f : e;
                        colacc[nt * 2 + cc] += same ? 0.f : e;
                        if (same) {
                            int jg = jgBase + nt * 8 + cc;
                            if (!isDiag || jg != ig) {
                                float sim = dot * INV_T;
                                int sl = atomicAdd(&g_pcnt[ig], 1);
                                if (sl < CAPR) g_posv[ig * CAPR + sl] = sim;
                                if (!isDiag) {
                                    int sl2 = atomicAdd(&g_pcnt[jg], 1);
                                    if (sl2 < CAPR) g_posv[jg * CAPR + sl2] = sim;
                                }
                            }
                        }
                    }
                na += __shfl_xor_sync(0xffffffffu, na, 1);
                na += __shfl_xor_sync(0xffffffffu, na, 2);
                if ((lane & 3) == 0) s_rowRed[rloc][wn] = na;
            }

        if (!isDiag) {
            #pragma unroll
            for (int idx = 0; idx < 4; idx++) {
                colacc[idx] += __shfl_xor_sync(0xffffffffu, colacc[idx], 4);
                colacc[idx] += __shfl_xor_sync(0xffffffffu, colacc[idx], 8);
                colacc[idx] += __shfl_xor_sync(0xffffffffu, colacc[idx], 16);
            }
            if (lane < 4) {
                #pragma unroll
                for (int nt = 0; nt < 2; nt++)
                    #pragma unroll
                    for (int cc = 0; cc < 2; cc++)
                        s_colRed[wn * 16 + nt * 8 + lane * 2 + cc][wm] =
                            colacc[nt * 2 + cc];
            }
        }
        __syncthreads();

        if (tid < 128) {
            float v = 0.f;
            #pragma unroll
            for (int k = 0; k < 8; k++) v += s_rowRed[tid][k];
            atomicAdd(&g_negS[ib * 128 + tid], v);
            if (!isDiag) {
                float w = s_colRed[tid][0] + s_colRed[tid][1];
                atomicAdd(&g_negS[jb * 128 + tid], w);
            }
        }

        // A switch for next unit
        if (hasNext && nib != ib) {
            cp_tile(bufA, nib * 128);
            CP_COMMIT();
            if (tid < 128) s_pi[tid] = g_pieces[nib * 128 + tid];
        }
        ib = nib; jb = njb;
    }
}

// ---------------- kernel 3: ranking loss partials ----------------
__global__ void ranking_kernel(const float* __restrict__ logits,
                               const float* __restrict__ la,
                               const float* __restrict__ lb) {
    __shared__ float ssum[256];
    __shared__ int   scnt[256];
    int tid = threadIdx.x;
    float sum = 0.f; int cnt = 0;
    for (int i = blockIdx.x * 256 + tid; i < BATCH * NDIMS; i += 64 * 256) {
        float diff = la[i] - lb[i];
        if (fabsf(diff) >= 0.05f) {
            float t = (diff > 0.f ? 0.9f : 0.f) + 0.05f;
            float l = logits[i];
            sum += fmaxf(l, 0.f) - l * t + log1pf(__expf(-fabsf(l)));
            cnt++;
        }
    }
    ssum[tid] = sum; scnt[tid] = cnt;
    __syncthreads();
    for (int o = 128; o; o >>= 1) {
        if (tid < o) { ssum[tid] += ssum[tid + o]; scnt[tid] += scnt[tid + o]; }
        __syncthreads();
    }
    if (tid == 0) { g_rankS[blockIdx.x] = ssum[0]; g_rankC[blockIdx.x] = scnt[0]; }
}

// ---------------- kernel 4: per-row merge (warp per row) ----------------
__global__ void final_row_kernel() {
    const int warp = threadIdx.x >> 5;
    const int lane = threadIdx.x & 31;
    const int i = blockIdx.x * 8 + warp;

    float S = __shfl_sync(0xffffffffu, (lane == 0) ? g_negS[i] : 0.f, 0);
    int n = g_pcnt[i];
    if (n > CAPR) n = CAPR;
    float sum = 0.f;
    int cnt = 0;
    if (S > 0.f) {
        float nl = INV_T + logf(S);
        cnt = n;
        for (int s = lane; s < n; s += 32) {
            float d = nl - g_posv[i * CAPR + s];
            sum += (d > 0.f) ? (d + log1pf(__expf(-d))) : log1pf(__expf(d));
        }
    }
    #pragma unroll
    for (int o = 16; o; o >>= 1) sum += __shfl_xor_sync(0xffffffffu, sum, o);
    if (lane == 0) { g_rowSum[i] = sum; g_rowCnt[i] = cnt; }
}

// ---------------- kernel 5: final deterministic reduce ----------------
__global__ void final_kernel(float* __restrict__ out, int out_size) {
    __shared__ float ssum[256];
    __shared__ int   scnt[256];
    int tid = threadIdx.x;
    float sum = 0.f; int cnt = 0;
    for (int i = tid; i < NROWS; i += 256) { sum += g_rowSum[i]; cnt += g_rowCnt[i]; }
    ssum[tid] = sum; scnt[tid] = cnt;
    __syncthreads();
    for (int o = 128; o; o >>= 1) {
        if (tid < o) { ssum[tid] += ssum[tid + o]; scnt[tid] += scnt[tid + o]; }
        __syncthreads();
    }
    if (tid == 0) {
        float rs = 0.f; int rc = 0;
        for (int b = 0; b < 64; b++) { rs += g_rankS[b]; rc += g_rankC[b]; }
        float lcon  = (scnt[0] > 0) ? (ssum[0] / (float)scnt[0]) : 0.f;
        float lrank = (rc > 0) ? (rs / (float)rc) : 0.f;
        out[0] = lrank + 0.3f * lcon;
        if (out_size > 1) out[1] = lrank;
        if (out_size > 2) out[2] = lcon;
    }
}

// ---------------- launch ----------------
extern "C" void kernel_launch(void* const* d_in, const int* in_sizes, int n_in,
                              void* d_out, int out_size) {
    const float* za     = (const float*)d_in[0];
    const float* zb     = (const float*)d_in[1];
    const float* logits = (const float*)d_in[2];
    const float* la     = (const float*)d_in[3];
    const float* lb     = (const float*)d_in[4];
    const int*   pa     = (const int*)d_in[5];
    const int*   pb     = (const int*)d_in[6];
    float* out = (float*)d_out;

    const int dynSmem = 3 * TILEB;   // A + B0 + B1 = 98304 bytes
    cudaFuncSetAttribute(simlse_kernel,
                         cudaFuncAttributeMaxDynamicSharedMemorySize, dynSmem);

    normalize_kernel<<<NROWS / 8, 256>>>(za, zb, pa, pb);
    ranking_kernel<<<64, 256>>>(logits, la, lb);
    simlse_kernel<<<NCTA, NTHREADS, dynSmem>>>();
    final_row_kernel<<<NROWS / 8, 256>>>();
    final_kernel<<<1, 256>>>(out, out_size);
}